// round 13
// baseline (speedup 1.0000x reference)
#include <cuda_runtime.h>
#include <cuda_fp16.h>
#include <math.h>
#include <stdint.h>

#define BB      4
#define LL      288
#define NNH     170
#define DDIM    128
#define WSZ     12
#define SHIFTSZ 6
#define HIDD    512
#define NWIN    24
#define MTOK    (BB * LL * NNH)   // 195840

// ---------------- scratch (fp16 activations) ----------------
__device__ __align__(256) __half g_xh[(size_t)MTOK * 128];
__device__ __align__(256) __half g_qkv[(size_t)MTOK * 384];
__device__ __align__(256) __half g_attn[(size_t)MTOK * 128];
__device__ __align__(256) __half g_x1h[(size_t)MTOK * 128];
__device__ __align__(256) __half g_h[(size_t)MTOK * 512];
// transposed weights [N][K], fp16
#define OFF_QKV  0
#define OFF_PROJ 49152
#define OFF_FC1  65536
#define OFF_FC2  131072
#define W_TOTAL  196608
__device__ __align__(256) __half g_w[W_TOTAL];

// ---------------- helpers ----------------
__device__ __forceinline__ uint32_t smem_u32(const void* p) {
    uint32_t a;
    asm("{ .reg .u64 t; cvta.to.shared.u64 t, %1; cvt.u32.u64 %0, t; }" : "=r"(a) : "l"(p));
    return a;
}
__device__ __forceinline__ void ldm4(uint32_t* r, uint32_t addr) {
    asm volatile("ldmatrix.sync.aligned.m8n8.x4.shared.b16 {%0,%1,%2,%3}, [%4];"
        : "=r"(r[0]), "=r"(r[1]), "=r"(r[2]), "=r"(r[3]) : "r"(addr));
}
__device__ __forceinline__ void mma16816(float* d, const uint32_t* a, uint32_t b0, uint32_t b1) {
    asm volatile("mma.sync.aligned.m16n8k16.row.col.f32.f16.f16.f32 "
        "{%0,%1,%2,%3}, {%4,%5,%6,%7}, {%8,%9}, {%0,%1,%2,%3};"
        : "+f"(d[0]), "+f"(d[1]), "+f"(d[2]), "+f"(d[3])
        : "r"(a[0]), "r"(a[1]), "r"(a[2]), "r"(a[3]), "r"(b0), "r"(b1));
}
#define CP16(dst, src) \
    asm volatile("cp.async.cg.shared.global [%0], [%1], 16;" :: "r"(dst), "l"(src) : "memory")
#define CPCOMMIT() asm volatile("cp.async.commit_group;" ::: "memory")

// stage: A 64x128B (swizzled) + B 128x128B (swizzled)
#define A_T     8192
#define B_T     16384
#define STAGE   (A_T + B_T)            // 24576
#define EPI_B   32768                  // 64 x 128 fp32 (permuted)
#define SM_G    (2 * STAGE > EPI_B ? 2 * STAGE : EPI_B)   // 49152

// ---------------------------------------------------------------------------
// Streaming HMMA GEMM: CTA 64x128, 128 thr, 4 warps 2m x 2n, warp tile 32x64.
// 0.375 LDSM/MMA (was 0.5) + 4 CTAs/SM (was 3).
// MODE 0: A = g_xh;   epi = +bias -> g_qkv                      (K=128, N=384)
// MODE 1: A = g_attn; epi = unshift + LN1 + residual(x) -> x1h  (K=128, N=128)
// MODE 2: A = g_x1h;  epi = GELU -> g_h                          (K=128, N=512)
// MODE 3: A = g_h;    epi = LN2 + residual(x1h) -> out fp32      (K=512, N=128)
// ---------------------------------------------------------------------------
template<int MODE, int K>
__global__ __launch_bounds__(128, 4)
void tc_gemm(int woff, const float* __restrict__ bias, float* __restrict__ outp,
             const float* __restrict__ xin, const float* __restrict__ gamma,
             const float* __restrict__ beta)
{
    constexpr int NC = K / 64;

    extern __shared__ __align__(1024) char smem[];
    const uint32_t sb = smem_u32(smem);
    const int tid = threadIdx.x;
    const int lane = tid & 31;
    const int wid = tid >> 5;          // 0..3
    const int wm = wid & 1;            // 2 m-blocks of 32
    const int wn = wid >> 1;           // 2 n-blocks of 64
    const int rowBlock = blockIdx.x * 64;
    const int colBlock = blockIdx.y * 128;

    const __half* asrc;
    if (MODE == 0) asrc = g_xh;
    else if (MODE == 1) asrc = g_attn;
    else if (MODE == 2) asrc = g_x1h;
    else asrc = g_h;
    const __half* wsrc = g_w + woff;

    const int lcc  = tid & 7;          // 16B chunk column
    const int lrow = tid >> 3;         // 0..15
    const uint32_t swo = (uint32_t)(lcc ^ (lrow & 7)) * 16;

    float acc[2][8][4];
    #pragma unroll
    for (int mt = 0; mt < 2; mt++)
        #pragma unroll
        for (int nt = 0; nt < 8; nt++)
            #pragma unroll
            for (int e = 0; e < 4; e++) acc[mt][nt][e] = 0.f;

    auto load_stage = [&](int ch, int s) {
        const int k0 = ch * 64 + lcc * 8;
        const uint32_t sA = sb + (uint32_t)s * STAGE;
        #pragma unroll
        for (int j = 0; j < 4; j++) {
            const int row = lrow + 16 * j;
            CP16(sA + (uint32_t)row * 128 + swo, asrc + (size_t)(rowBlock + row) * K + k0);
        }
        #pragma unroll
        for (int j = 0; j < 8; j++) {
            const int row = lrow + 16 * j;
            CP16(sA + A_T + (uint32_t)row * 128 + swo, wsrc + (size_t)(colBlock + row) * K + k0);
        }
        CPCOMMIT();
    };

    const int lmRow = lane & 15;
    const int lmHalf = lane >> 4;

    load_stage(0, 0);
    for (int ch = 0; ch < NC; ch++) {
        if (ch + 1 < NC) {
            load_stage(ch + 1, (ch + 1) & 1);
            asm volatile("cp.async.wait_group 1;" ::: "memory");
        } else {
            asm volatile("cp.async.wait_group 0;" ::: "memory");
        }
        __syncthreads();

        const uint32_t sA = sb + (uint32_t)(ch & 1) * STAGE;
        const uint32_t sB = sA + A_T;
        #pragma unroll
        for (int kk = 0; kk < 4; kk++) {
            const int chk = kk * 2 + lmHalf;
            uint32_t af[2][4], bf[4][4];
            #pragma unroll
            for (int mt = 0; mt < 2; mt++) {
                const int rA = wm * 32 + mt * 16 + lmRow;
                ldm4(af[mt], sA + (uint32_t)rA * 128 + (uint32_t)((chk ^ (rA & 7)) * 16));
            }
            #pragma unroll
            for (int pt = 0; pt < 4; pt++) {
                const int rB = wn * 64 + pt * 16 + lmRow;
                ldm4(bf[pt], sB + (uint32_t)rB * 128 + (uint32_t)((chk ^ (rB & 7)) * 16));
            }
            #pragma unroll
            for (int mt = 0; mt < 2; mt++)
                #pragma unroll
                for (int nt = 0; nt < 8; nt++)
                    mma16816(acc[mt][nt], af[mt], bf[nt >> 1][nt & 1], bf[nt >> 1][(nt & 1) + 2]);
        }
        __syncthreads();
    }

    if (MODE == 0 || MODE == 2) {
        const int ld = (MODE == 0) ? 384 : 512;
        __half* base = (MODE == 0) ? g_qkv : g_h;
        #pragma unroll
        for (int mt = 0; mt < 2; mt++) {
            const int r0 = rowBlock + wm * 32 + mt * 16 + (lane >> 2);
            #pragma unroll
            for (int nt = 0; nt < 8; nt++) {
                const int c = colBlock + wn * 64 + nt * 8 + (lane & 3) * 2;
                const float b0 = bias[c], b1 = bias[c + 1];
                #pragma unroll
                for (int hh = 0; hh < 2; hh++) {
                    const int r = r0 + hh * 8;
                    float v0 = acc[mt][nt][hh * 2 + 0] + b0;
                    float v1 = acc[mt][nt][hh * 2 + 1] + b1;
                    if (MODE == 2) { v0 *= normcdff(v0); v1 *= normcdff(v1); }
                    *(__half2*)(base + (size_t)r * ld + c) = __floats2half2_rn(v0, v1);
                }
            }
        }
        return;
    }

    // LN modes (1 and 3): permuted fp32 staging + warp-per-row epilogue
    float* sf = (float*)smem;
    #pragma unroll
    for (int mt = 0; mt < 2; mt++) {
        #pragma unroll
        for (int nt = 0; nt < 8; nt++) {
            const int r0 = wm * 32 + mt * 16 + (lane >> 2);
            const int c  = wn * 64 + nt * 8 + (lane & 3) * 2;
            const int p0 = (c + 8 * r0) & 127;
            *(float2*)(sf + r0 * 128 + p0) = make_float2(acc[mt][nt][0], acc[mt][nt][1]);
            const int r1 = r0 + 8;
            const int p1 = (c + 8 * r1) & 127;
            *(float2*)(sf + r1 * 128 + p1) = make_float2(acc[mt][nt][2], acc[mt][nt][3]);
        }
    }
    __syncthreads();

    #pragma unroll 1
    for (int rr = 0; rr < 16; rr++) {
        const int lr = wid * 16 + rr;
        const int r  = rowBlock + lr;
        float4 v = *(float4*)(sf + lr * 128 + lane * 4);
        const int col = (lane * 4 - lr * 8) & 127;
        const float4 bv = *(const float4*)(bias + col);
        v.x += bv.x; v.y += bv.y; v.z += bv.z; v.w += bv.w;

        float s  = v.x + v.y + v.z + v.w;
        float s2 = v.x * v.x + v.y * v.y + v.z * v.z + v.w * v.w;
        #pragma unroll
        for (int off = 16; off > 0; off >>= 1) {
            s  += __shfl_xor_sync(0xFFFFFFFFu, s,  off);
            s2 += __shfl_xor_sync(0xFFFFFFFFu, s2, off);
        }
        const float mean = s * (1.f / 128.f);
        const float var  = fmaxf(s2 * (1.f / 128.f) - mean * mean, 0.f);
        const float rstd = rsqrtf(var + 1e-5f);

        const float4 gv = *(const float4*)(gamma + col);
        const float4 be = *(const float4*)(beta + col);

        int b = r / (NNH * LL), rem = r % (NNH * LL);
        int n = rem / LL, li = rem % LL;

        if (MODE == 1) {
            int lo_ = li - SHIFTSZ; if (lo_ < 0) lo_ += LL;
            const float4 res = *(const float4*)(xin + ((size_t)(b * LL + lo_) * NNH + n) * DDIM + col);
            float y0 = (v.x - mean) * rstd * gv.x + be.x + res.x;
            float y1 = (v.y - mean) * rstd * gv.y + be.y + res.y;
            float y2 = (v.z - mean) * rstd * gv.z + be.z + res.z;
            float y3 = (v.w - mean) * rstd * gv.w + be.w + res.w;
            __align__(8) __half hv[4];
            hv[0] = __float2half_rn(y0); hv[1] = __float2half_rn(y1);
            hv[2] = __float2half_rn(y2); hv[3] = __float2half_rn(y3);
            *(uint2*)(g_x1h + ((size_t)(b * NNH + n) * LL + lo_) * DDIM + col) = *(uint2*)hv;
        } else {
            const uint2 rh = *(const uint2*)(g_x1h + (size_t)r * 128 + col);
            const __half* rp = (const __half*)&rh;
            float4 o;
            o.x = (v.x - mean) * rstd * gv.x + be.x + __half2float(rp[0]);
            o.y = (v.y - mean) * rstd * gv.y + be.y + __half2float(rp[1]);
            o.z = (v.z - mean) * rstd * gv.z + be.z + __half2float(rp[2]);
            o.w = (v.w - mean) * rstd * gv.w + be.w + __half2float(rp[3]);
            *(float4*)(outp + ((size_t)(b * LL + li) * NNH + n) * DDIM + col) = o;
        }
    }
}

// ---------------------------------------------------------------------------
// prep_x: x (B,L,N,D fp32) -> g_xh (b,n,ls) fp16 with shift fused.
// ---------------------------------------------------------------------------
__global__ __launch_bounds__(256)
void prep_x(const float* __restrict__ x)
{
    const int row = blockIdx.x * 8 + (threadIdx.x >> 5);
    const int lane = threadIdx.x & 31;
    int b = row / (NNH * LL), rem = row % (NNH * LL);
    int n = rem / LL, ls = rem % LL;
    int l = ls - SHIFTSZ; if (l < 0) l += LL;
    const float4 v = *(const float4*)(x + ((size_t)(b * LL + l) * NNH + n) * DDIM + lane * 4);
    __align__(8) __half hv[4];
    hv[0] = __float2half_rn(v.x); hv[1] = __float2half_rn(v.y);
    hv[2] = __float2half_rn(v.z); hv[3] = __float2half_rn(v.w);
    *(uint2*)(g_xh + (size_t)row * 128 + lane * 4) = *(uint2*)hv;
}

// ---------------------------------------------------------------------------
// Weight prep: fp32 [K][N] -> transposed fp16 [N][K]
// ---------------------------------------------------------------------------
__global__ void prep_w(const float* __restrict__ qkv_w, const float* __restrict__ proj_w,
                       const float* __restrict__ fc1_w, const float* __restrict__ fc2_w)
{
    int idx = blockIdx.x * 256 + threadIdx.x;
    if (idx >= W_TOTAL) return;
    const float* src; int K, N, base;
    if (idx < OFF_PROJ)      { src = qkv_w;  K = 128; N = 384; base = OFF_QKV;  }
    else if (idx < OFF_FC1)  { src = proj_w; K = 128; N = 128; base = OFF_PROJ; }
    else if (idx < OFF_FC2)  { src = fc1_w;  K = 128; N = 512; base = OFF_FC1;  }
    else                     { src = fc2_w;  K = 512; N = 128; base = OFF_FC2;  }
    int local = idx - base;
    int nn = local / K, kk = local % K;
    g_w[idx] = __float2half_rn(src[(size_t)kk * N + nn]);
}

// ---------------------------------------------------------------------------
// Windowed attention (round-12 champion): 192 threads = 4 windows x 48
// threads (8 heads x 6 row-pairs). fp16 smem; k/v loaded+converted once/2rows.
// ---------------------------------------------------------------------------
__global__ __launch_bounds__(192)
void attn_kernel()
{
    __shared__ __half s[4][12 * 384];   // 36 KB

    const int blk = blockIdx.x;
    const int wp  = blk % (NWIN / 4);
    const int rem = blk / (NWIN / 4);
    const int n   = rem % NNH;
    const int b   = rem / NNH;
    const int tid = threadIdx.x;

    const size_t qbase = ((size_t)(b * NNH + n) * LL + wp * 48) * 384;
    {
        const uint4* src = (const uint4*)(g_qkv + qbase);
        uint4* dst = (uint4*)(&s[0][0]);
        #pragma unroll
        for (int v = 0; v < 12; v++)
            dst[tid + v * 192] = src[tid + v * 192];
    }
    __syncthreads();

    const int win = tid / 48;
    const int t   = tid % 48;
    const int h   = t / 6;
    const int rp  = t % 6;
    const int i0  = rp * 2;
    const int i1  = i0 + 1;
    const int w   = wp * 4 + win;
    const __half* sp = s[win];
    const bool gi = (i0 < SHIFTSZ);
    const bool masked = (w == 0);

    float q0[16], q1[16];
    #pragma unroll
    for (int e = 0; e < 2; e++) {
        uint4 a = *(const uint4*)(sp + i0 * 384 + h * 16 + e * 8);
        uint4 c = *(const uint4*)(sp + i1 * 384 + h * 16 + e * 8);
        const __half2* pa = (const __half2*)&a;
        const __half2* pc = (const __half2*)&c;
        #pragma unroll
        for (int u = 0; u < 4; u++) {
            float2 fa = __half22float2(pa[u]);
            float2 fc = __half22float2(pc[u]);
            q0[e * 8 + u * 2] = fa.x; q0[e * 8 + u * 2 + 1] = fa.y;
            q1[e * 8 + u * 2] = fc.x; q1[e * 8 + u * 2 + 1] = fc.y;
        }
    }

    float sc0[12], sc1[12];
    float mx0 = -1e30f, mx1 = -1e30f;
    #pragma unroll
    for (int j = 0; j < 12; j++) {
        uint4 ka = *(const uint4*)(sp + j * 384 + 128 + h * 16);
        uint4 kb = *(const uint4*)(sp + j * 384 + 128 + h * 16 + 8);
        const __half2* pa = (const __half2*)&ka;
        const __half2* pb = (const __half2*)&kb;
        float a0 = 0.f, a1 = 0.f;
        #pragma unroll
        for (int u = 0; u < 4; u++) {
            float2 fa = __half22float2(pa[u]);
            float2 fb = __half22float2(pb[u]);
            a0 += q0[u * 2] * fa.x + q0[u * 2 + 1] * fa.y
                + q0[8 + u * 2] * fb.x + q0[8 + u * 2 + 1] * fb.y;
            a1 += q1[u * 2] * fa.x + q1[u * 2 + 1] * fa.y
                + q1[8 + u * 2] * fb.x + q1[8 + u * 2 + 1] * fb.y;
        }
        a0 *= 0.25f; a1 *= 0.25f;
        if (masked && (gi != (j < SHIFTSZ))) { a0 -= 100.f; a1 -= 100.f; }
        sc0[j] = a0; mx0 = fmaxf(mx0, a0);
        sc1[j] = a1; mx1 = fmaxf(mx1, a1);
    }
    float den0 = 0.f, den1 = 0.f;
    #pragma unroll
    for (int j = 0; j < 12; j++) {
        sc0[j] = __expf(sc0[j] - mx0); den0 += sc0[j];
        sc1[j] = __expf(sc1[j] - mx1); den1 += sc1[j];
    }
    const float inv0 = 1.f / den0;
    const float inv1 = 1.f / den1;

    float o0[16], o1[16];
    #pragma unroll
    for (int d = 0; d < 16; d++) { o0[d] = 0.f; o1[d] = 0.f; }
    #pragma unroll
    for (int j = 0; j < 12; j++) {
        const float p0 = sc0[j] * inv0;
        const float p1 = sc1[j] * inv1;
        uint4 va = *(const uint4*)(sp + j * 384 + 256 + h * 16);
        uint4 vb = *(const uint4*)(sp + j * 384 + 256 + h * 16 + 8);
        const __half2* pa = (const __half2*)&va;
        const __half2* pb = (const __half2*)&vb;
        #pragma unroll
        for (int u = 0; u < 4; u++) {
            float2 fa = __half22float2(pa[u]);
            float2 fb = __half22float2(pb[u]);
            o0[u * 2] += p0 * fa.x;     o0[u * 2 + 1] += p0 * fa.y;
            o0[8 + u * 2] += p0 * fb.x; o0[8 + u * 2 + 1] += p0 * fb.y;
            o1[u * 2] += p1 * fa.x;     o1[u * 2 + 1] += p1 * fa.y;
            o1[8 + u * 2] += p1 * fb.x; o1[8 + u * 2 + 1] += p1 * fb.y;
        }
    }

    const size_t rowbase = (size_t)(b * NNH + n) * LL + (size_t)w * WSZ;
    __align__(16) __half hv[16];
    #pragma unroll
    for (int d = 0; d < 8; d++)
        *(__half2*)(hv + d * 2) = __floats2half2_rn(o0[d * 2], o0[d * 2 + 1]);
    __half* d0 = g_attn + (rowbase + i0) * 128 + h * 16;
    *(uint4*)(d0)     = *(uint4*)(hv);
    *(uint4*)(d0 + 8) = *(uint4*)(hv + 8);
    #pragma unroll
    for (int d = 0; d < 8; d++)
        *(__half2*)(hv + d * 2) = __floats2half2_rn(o1[d * 2], o1[d * 2 + 1]);
    __half* d1 = g_attn + (rowbase + i1) * 128 + h * 16;
    *(uint4*)(d1)     = *(uint4*)(hv);
    *(uint4*)(d1 + 8) = *(uint4*)(hv + 8);
}

// ---------------------------------------------------------------------------
extern "C" void kernel_launch(void* const* d_in, const int* in_sizes, int n_in,
                              void* d_out, int out_size)
{
    const float* x      = (const float*)d_in[0];
    const float* qkv_w  = (const float*)d_in[1];
    const float* qkv_b  = (const float*)d_in[2];
    const float* proj_w = (const float*)d_in[3];
    const float* proj_b = (const float*)d_in[4];
    const float* fc1_w  = (const float*)d_in[5];
    const float* fc1_b  = (const float*)d_in[6];
    const float* fc2_w  = (const float*)d_in[7];
    const float* fc2_b  = (const float*)d_in[8];
    const float* g1     = (const float*)d_in[9];
    const float* b1     = (const float*)d_in[10];
    const float* g2     = (const float*)d_in[11];
    const float* b2     = (const float*)d_in[12];
    float* out = (float*)d_out;

    static bool attr_done = false;
    if (!attr_done) {
        cudaFuncSetAttribute(tc_gemm<0, 128>, cudaFuncAttributeMaxDynamicSharedMemorySize, SM_G);
        cudaFuncSetAttribute(tc_gemm<1, 128>, cudaFuncAttributeMaxDynamicSharedMemorySize, SM_G);
        cudaFuncSetAttribute(tc_gemm<2, 128>, cudaFuncAttributeMaxDynamicSharedMemorySize, SM_G);
        cudaFuncSetAttribute(tc_gemm<3, 512>, cudaFuncAttributeMaxDynamicSharedMemorySize, SM_G);
        attr_done = true;
    }

    const int MB = MTOK / 64; // 3060

    // 0) weight transpose to fp16 [N][K]; x gather/shift to fp16
    prep_w<<<(W_TOTAL + 255) / 256, 256>>>(qkv_w, proj_w, fc1_w, fc2_w);
    prep_x<<<MTOK / 8, 256>>>(x);
    // 1) QKV projection (streaming, 3 column blocks)
    tc_gemm<0, 128><<<dim3(MB, 3), 128, SM_G>>>(OFF_QKV, qkv_b, nullptr, nullptr, nullptr, nullptr);
    // 2) windowed attention (4 windows per block, fp16 smem, row-pair reuse)
    attn_kernel<<<BB * NNH * (NWIN / 4), 192>>>();
    // 3) proj + unshift + LN1 + residual(x)
    tc_gemm<1, 128><<<dim3(MB, 1), 128, SM_G>>>(OFF_PROJ, proj_b, nullptr, x, g1, b1);
    // 4) fc1 + GELU
    tc_gemm<2, 128><<<dim3(MB, 4), 128, SM_G>>>(OFF_FC1, fc1_b, nullptr, nullptr, nullptr, nullptr);
    // 5) fc2 + LN2 + residual(x1h) + scatter to (B,L,N,D)
    tc_gemm<3, 512><<<dim3(MB, 1), 128, SM_G>>>(OFF_FC2, fc2_b, out, nullptr, g2, b2);
}

// round 14
// speedup vs baseline: 1.0615x; 1.0615x over previous
#include <cuda_runtime.h>
#include <cuda_fp16.h>
#include <math.h>
#include <stdint.h>

#define BB      4
#define LL      288
#define NNH     170
#define DDIM    128
#define WSZ     12
#define SHIFTSZ 6
#define HIDD    512
#define NWIN    24
#define MTOK    (BB * LL * NNH)   // 195840

// ---------------- scratch (fp16 activations) ----------------
__device__ __align__(256) __half g_xh[(size_t)MTOK * 128];
__device__ __align__(256) __half g_qkv[(size_t)MTOK * 384];
__device__ __align__(256) __half g_attn[(size_t)MTOK * 128];
__device__ __align__(256) __half g_x1h[(size_t)MTOK * 128];
__device__ __align__(256) __half g_h[(size_t)MTOK * 512];
// transposed weights [N][K], fp16
#define OFF_QKV  0
#define OFF_PROJ 49152
#define OFF_FC1  65536
#define OFF_FC2  131072
#define W_TOTAL  196608
__device__ __align__(256) __half g_w[W_TOTAL];

// ---------------- helpers ----------------
__device__ __forceinline__ uint32_t smem_u32(const void* p) {
    uint32_t a;
    asm("{ .reg .u64 t; cvta.to.shared.u64 t, %1; cvt.u32.u64 %0, t; }" : "=r"(a) : "l"(p));
    return a;
}
__device__ __forceinline__ void ldm4(uint32_t* r, uint32_t addr) {
    asm volatile("ldmatrix.sync.aligned.m8n8.x4.shared.b16 {%0,%1,%2,%3}, [%4];"
        : "=r"(r[0]), "=r"(r[1]), "=r"(r[2]), "=r"(r[3]) : "r"(addr));
}
__device__ __forceinline__ void mma16816(float* d, const uint32_t* a, uint32_t b0, uint32_t b1) {
    asm volatile("mma.sync.aligned.m16n8k16.row.col.f32.f16.f16.f32 "
        "{%0,%1,%2,%3}, {%4,%5,%6,%7}, {%8,%9}, {%0,%1,%2,%3};"
        : "+f"(d[0]), "+f"(d[1]), "+f"(d[2]), "+f"(d[3])
        : "r"(a[0]), "r"(a[1]), "r"(a[2]), "r"(a[3]), "r"(b0), "r"(b1));
}
#define CP16(dst, src) \
    asm volatile("cp.async.cg.shared.global [%0], [%1], 16;" :: "r"(dst), "l"(src) : "memory")
#define CPCOMMIT() asm volatile("cp.async.commit_group;" ::: "memory")

// stage: A 64x128B (swizzled) + B 128x128B (swizzled)
#define A_T     8192
#define B_T     16384
#define STAGE   (A_T + B_T)            // 24576
#define EPI_B   32768                  // 64 x 128 fp32 (permuted)
#define SM128   (2 * STAGE > EPI_B ? 2 * STAGE : EPI_B)   // 49152
#define SM512   (3 * STAGE)                                // 73728

// ---------------------------------------------------------------------------
// Streaming HMMA GEMM (round-12 proven): CTA 64x128, 8 warps 2m x 4n.
// MODE 0: A = g_xh;   epi = +bias -> g_qkv                       (K=128, N=384)
// MODE 1: A = g_attn; epi = unshift + LN1 + residual(g_xh) -> x1h (K=128, N=128)
// MODE 2: A = g_x1h;  epi = GELU -> g_h                           (K=128, N=512)
// MODE 3: A = g_h;    epi = LN2 + residual(x1h) -> out fp32       (K=512, N=128)
// ---------------------------------------------------------------------------
template<int MODE, int K>
__global__ __launch_bounds__(256, 3)
void tc_gemm(int woff, const float* __restrict__ bias, float* __restrict__ outp,
             const float* __restrict__ gamma, const float* __restrict__ beta)
{
    constexpr int NC = K / 64;
    constexpr int STAGES = (NC >= 3) ? 3 : 2;

    extern __shared__ __align__(1024) char smem[];
    const uint32_t sb = smem_u32(smem);
    const int tid = threadIdx.x;
    const int lane = tid & 31;
    const int wid = tid >> 5;
    const int wm = wid & 1;
    const int wn = wid >> 1;
    const int rowBlock = blockIdx.x * 64;
    const int colBlock = blockIdx.y * 128;

    const __half* asrc;
    if (MODE == 0) asrc = g_xh;
    else if (MODE == 1) asrc = g_attn;
    else if (MODE == 2) asrc = g_x1h;
    else asrc = g_h;
    const __half* wsrc = g_w + woff;

    const int lcc  = tid & 7;
    const int lrow = tid >> 3;
    const uint32_t swo = (uint32_t)(lcc ^ (lrow & 7)) * 16;

    float acc[2][4][4];
    #pragma unroll
    for (int mt = 0; mt < 2; mt++)
        #pragma unroll
        for (int nt = 0; nt < 4; nt++)
            #pragma unroll
            for (int e = 0; e < 4; e++) acc[mt][nt][e] = 0.f;

    auto load_stage = [&](int ch, int s) {
        const int k0 = ch * 64 + lcc * 8;
        const uint32_t sA = sb + (uint32_t)s * STAGE;
        #pragma unroll
        for (int j = 0; j < 2; j++) {
            const int row = lrow + 32 * j;
            CP16(sA + (uint32_t)row * 128 + swo, asrc + (size_t)(rowBlock + row) * K + k0);
        }
        #pragma unroll
        for (int j = 0; j < 4; j++) {
            const int row = lrow + 32 * j;
            CP16(sA + A_T + (uint32_t)row * 128 + swo, wsrc + (size_t)(colBlock + row) * K + k0);
        }
        CPCOMMIT();
    };

    const int lmRow = lane & 15;
    const int lmHalf = lane >> 4;

    load_stage(0, 0);
    if (STAGES >= 3 && NC >= 2) load_stage(1, 1);

    for (int ch = 0; ch < NC; ch++) {
        const int nxt = ch + STAGES - 1;
        if (nxt < NC) {
            load_stage(nxt, nxt % STAGES);
            if (STAGES == 3) asm volatile("cp.async.wait_group 2;" ::: "memory");
            else             asm volatile("cp.async.wait_group 1;" ::: "memory");
        } else {
            if (STAGES == 3 && ch < NC - 1) asm volatile("cp.async.wait_group 1;" ::: "memory");
            else                             asm volatile("cp.async.wait_group 0;" ::: "memory");
        }
        __syncthreads();

        const uint32_t sA = sb + (uint32_t)(ch % STAGES) * STAGE;
        const uint32_t sB = sA + A_T;
        #pragma unroll
        for (int kk = 0; kk < 4; kk++) {
            const int chk = kk * 2 + lmHalf;
            uint32_t af[2][4], bf[2][4];
            #pragma unroll
            for (int mt = 0; mt < 2; mt++) {
                const int rA = wm * 32 + mt * 16 + lmRow;
                ldm4(af[mt], sA + (uint32_t)rA * 128 + (uint32_t)((chk ^ (rA & 7)) * 16));
            }
            #pragma unroll
            for (int pt = 0; pt < 2; pt++) {
                const int rB = wn * 32 + pt * 16 + lmRow;
                ldm4(bf[pt], sB + (uint32_t)rB * 128 + (uint32_t)((chk ^ (rB & 7)) * 16));
            }
            #pragma unroll
            for (int mt = 0; mt < 2; mt++)
                #pragma unroll
                for (int nt = 0; nt < 4; nt++)
                    mma16816(acc[mt][nt], af[mt], bf[nt >> 1][nt & 1], bf[nt >> 1][(nt & 1) + 2]);
        }
        __syncthreads();
    }

    if (MODE == 0 || MODE == 2) {
        const int ld = (MODE == 0) ? 384 : 512;
        __half* base = (MODE == 0) ? g_qkv : g_h;
        #pragma unroll
        for (int mt = 0; mt < 2; mt++) {
            const int r0 = rowBlock + wm * 32 + mt * 16 + (lane >> 2);
            #pragma unroll
            for (int nt = 0; nt < 4; nt++) {
                const int c = colBlock + wn * 32 + nt * 8 + (lane & 3) * 2;
                const float b0 = bias[c], b1 = bias[c + 1];
                #pragma unroll
                for (int hh = 0; hh < 2; hh++) {
                    const int r = r0 + hh * 8;
                    float v0 = acc[mt][nt][hh * 2 + 0] + b0;
                    float v1 = acc[mt][nt][hh * 2 + 1] + b1;
                    if (MODE == 2) { v0 *= normcdff(v0); v1 *= normcdff(v1); }
                    *(__half2*)(base + (size_t)r * ld + c) = __floats2half2_rn(v0, v1);
                }
            }
        }
        return;
    }

    // LN modes (1 and 3): permuted fp32 staging + warp-per-row epilogue
    float* sf = (float*)smem;
    #pragma unroll
    for (int mt = 0; mt < 2; mt++) {
        #pragma unroll
        for (int nt = 0; nt < 4; nt++) {
            const int r0 = wm * 32 + mt * 16 + (lane >> 2);
            const int c  = wn * 32 + nt * 8 + (lane & 3) * 2;
            const int p0 = (c + 8 * r0) & 127;
            *(float2*)(sf + r0 * 128 + p0) = make_float2(acc[mt][nt][0], acc[mt][nt][1]);
            const int r1 = r0 + 8;
            const int p1 = (c + 8 * r1) & 127;
            *(float2*)(sf + r1 * 128 + p1) = make_float2(acc[mt][nt][2], acc[mt][nt][3]);
        }
    }
    __syncthreads();

    #pragma unroll 1
    for (int rr = 0; rr < 8; rr++) {
        const int lr = wid * 8 + rr;
        const int r  = rowBlock + lr;
        float4 v = *(float4*)(sf + lr * 128 + lane * 4);
        const int col = (lane * 4 - lr * 8) & 127;
        const float4 bv = *(const float4*)(bias + col);
        v.x += bv.x; v.y += bv.y; v.z += bv.z; v.w += bv.w;

        float s  = v.x + v.y + v.z + v.w;
        float s2 = v.x * v.x + v.y * v.y + v.z * v.z + v.w * v.w;
        #pragma unroll
        for (int off = 16; off > 0; off >>= 1) {
            s  += __shfl_xor_sync(0xFFFFFFFFu, s,  off);
            s2 += __shfl_xor_sync(0xFFFFFFFFu, s2, off);
        }
        const float mean = s * (1.f / 128.f);
        const float var  = fmaxf(s2 * (1.f / 128.f) - mean * mean, 0.f);
        const float rstd = rsqrtf(var + 1e-5f);

        const float4 gv = *(const float4*)(gamma + col);
        const float4 be = *(const float4*)(beta + col);

        int b = r / (NNH * LL), rem = r % (NNH * LL);
        int n = rem / LL, li = rem % LL;

        if (MODE == 1) {
            // residual: x[b, li-SHIFT, n] == g_xh[r] (linear fp16, coalesced)
            int lo_ = li - SHIFTSZ; if (lo_ < 0) lo_ += LL;
            const uint2 rh = *(const uint2*)(g_xh + (size_t)r * 128 + col);
            const __half* rp = (const __half*)&rh;
            float y0 = (v.x - mean) * rstd * gv.x + be.x + __half2float(rp[0]);
            float y1 = (v.y - mean) * rstd * gv.y + be.y + __half2float(rp[1]);
            float y2 = (v.z - mean) * rstd * gv.z + be.z + __half2float(rp[2]);
            float y3 = (v.w - mean) * rstd * gv.w + be.w + __half2float(rp[3]);
            __align__(8) __half hv[4];
            hv[0] = __float2half_rn(y0); hv[1] = __float2half_rn(y1);
            hv[2] = __float2half_rn(y2); hv[3] = __float2half_rn(y3);
            *(uint2*)(g_x1h + ((size_t)(b * NNH + n) * LL + lo_) * DDIM + col) = *(uint2*)hv;
        } else {
            const uint2 rh = *(const uint2*)(g_x1h + (size_t)r * 128 + col);
            const __half* rp = (const __half*)&rh;
            float4 o;
            o.x = (v.x - mean) * rstd * gv.x + be.x + __half2float(rp[0]);
            o.y = (v.y - mean) * rstd * gv.y + be.y + __half2float(rp[1]);
            o.z = (v.z - mean) * rstd * gv.z + be.z + __half2float(rp[2]);
            o.w = (v.w - mean) * rstd * gv.w + be.w + __half2float(rp[3]);
            *(float4*)(outp + ((size_t)(b * LL + li) * NNH + n) * DDIM + col) = o;
        }
    }
}

// ---------------------------------------------------------------------------
// prep_x: x (B,L,N,D fp32) -> g_xh (b,n,ls) fp16 with shift fused.
// ---------------------------------------------------------------------------
__global__ __launch_bounds__(256)
void prep_x(const float* __restrict__ x)
{
    const int row = blockIdx.x * 8 + (threadIdx.x >> 5);
    const int lane = threadIdx.x & 31;
    int b = row / (NNH * LL), rem = row % (NNH * LL);
    int n = rem / LL, ls = rem % LL;
    int l = ls - SHIFTSZ; if (l < 0) l += LL;
    const float4 v = *(const float4*)(x + ((size_t)(b * LL + l) * NNH + n) * DDIM + lane * 4);
    __align__(8) __half hv[4];
    hv[0] = __float2half_rn(v.x); hv[1] = __float2half_rn(v.y);
    hv[2] = __float2half_rn(v.z); hv[3] = __float2half_rn(v.w);
    *(uint2*)(g_xh + (size_t)row * 128 + lane * 4) = *(uint2*)hv;
}

// ---------------------------------------------------------------------------
// Weight prep: fp32 [K][N] -> transposed fp16 [N][K]
// ---------------------------------------------------------------------------
__global__ void prep_w(const float* __restrict__ qkv_w, const float* __restrict__ proj_w,
                       const float* __restrict__ fc1_w, const float* __restrict__ fc2_w)
{
    int idx = blockIdx.x * 256 + threadIdx.x;
    if (idx >= W_TOTAL) return;
    const float* src; int K, N, base;
    if (idx < OFF_PROJ)      { src = qkv_w;  K = 128; N = 384; base = OFF_QKV;  }
    else if (idx < OFF_FC1)  { src = proj_w; K = 128; N = 128; base = OFF_PROJ; }
    else if (idx < OFF_FC2)  { src = fc1_w;  K = 128; N = 512; base = OFF_FC1;  }
    else                     { src = fc2_w;  K = 512; N = 128; base = OFF_FC2;  }
    int local = idx - base;
    int nn = local / K, kk = local % K;
    g_w[idx] = __float2half_rn(src[(size_t)kk * N + nn]);
}

// ---------------------------------------------------------------------------
// Windowed attention (round-12 champion): 192 threads = 4 windows x 48
// threads (8 heads x 6 row-pairs). fp16 smem; k/v loaded+converted once/2rows.
// ---------------------------------------------------------------------------
__global__ __launch_bounds__(192)
void attn_kernel()
{
    __shared__ __half s[4][12 * 384];   // 36 KB

    const int blk = blockIdx.x;
    const int wp  = blk % (NWIN / 4);
    const int rem = blk / (NWIN / 4);
    const int n   = rem % NNH;
    const int b   = rem / NNH;
    const int tid = threadIdx.x;

    const size_t qbase = ((size_t)(b * NNH + n) * LL + wp * 48) * 384;
    {
        const uint4* src = (const uint4*)(g_qkv + qbase);
        uint4* dst = (uint4*)(&s[0][0]);
        #pragma unroll
        for (int v = 0; v < 12; v++)
            dst[tid + v * 192] = src[tid + v * 192];
    }
    __syncthreads();

    const int win = tid / 48;
    const int t   = tid % 48;
    const int h   = t / 6;
    const int rp  = t % 6;
    const int i0  = rp * 2;
    const int i1  = i0 + 1;
    const int w   = wp * 4 + win;
    const __half* sp = s[win];
    const bool gi = (i0 < SHIFTSZ);
    const bool masked = (w == 0);

    float q0[16], q1[16];
    #pragma unroll
    for (int e = 0; e < 2; e++) {
        uint4 a = *(const uint4*)(sp + i0 * 384 + h * 16 + e * 8);
        uint4 c = *(const uint4*)(sp + i1 * 384 + h * 16 + e * 8);
        const __half2* pa = (const __half2*)&a;
        const __half2* pc = (const __half2*)&c;
        #pragma unroll
        for (int u = 0; u < 4; u++) {
            float2 fa = __half22float2(pa[u]);
            float2 fc = __half22float2(pc[u]);
            q0[e * 8 + u * 2] = fa.x; q0[e * 8 + u * 2 + 1] = fa.y;
            q1[e * 8 + u * 2] = fc.x; q1[e * 8 + u * 2 + 1] = fc.y;
        }
    }

    float sc0[12], sc1[12];
    float mx0 = -1e30f, mx1 = -1e30f;
    #pragma unroll
    for (int j = 0; j < 12; j++) {
        uint4 ka = *(const uint4*)(sp + j * 384 + 128 + h * 16);
        uint4 kb = *(const uint4*)(sp + j * 384 + 128 + h * 16 + 8);
        const __half2* pa = (const __half2*)&ka;
        const __half2* pb = (const __half2*)&kb;
        float a0 = 0.f, a1 = 0.f;
        #pragma unroll
        for (int u = 0; u < 4; u++) {
            float2 fa = __half22float2(pa[u]);
            float2 fb = __half22float2(pb[u]);
            a0 += q0[u * 2] * fa.x + q0[u * 2 + 1] * fa.y
                + q0[8 + u * 2] * fb.x + q0[8 + u * 2 + 1] * fb.y;
            a1 += q1[u * 2] * fa.x + q1[u * 2 + 1] * fa.y
                + q1[8 + u * 2] * fb.x + q1[8 + u * 2 + 1] * fb.y;
        }
        a0 *= 0.25f; a1 *= 0.25f;
        if (masked && (gi != (j < SHIFTSZ))) { a0 -= 100.f; a1 -= 100.f; }
        sc0[j] = a0; mx0 = fmaxf(mx0, a0);
        sc1[j] = a1; mx1 = fmaxf(mx1, a1);
    }
    float den0 = 0.f, den1 = 0.f;
    #pragma unroll
    for (int j = 0; j < 12; j++) {
        sc0[j] = __expf(sc0[j] - mx0); den0 += sc0[j];
        sc1[j] = __expf(sc1[j] - mx1); den1 += sc1[j];
    }
    const float inv0 = 1.f / den0;
    const float inv1 = 1.f / den1;

    float o0[16], o1[16];
    #pragma unroll
    for (int d = 0; d < 16; d++) { o0[d] = 0.f; o1[d] = 0.f; }
    #pragma unroll
    for (int j = 0; j < 12; j++) {
        const float p0 = sc0[j] * inv0;
        const float p1 = sc1[j] * inv1;
        uint4 va = *(const uint4*)(sp + j * 384 + 256 + h * 16);
        uint4 vb = *(const uint4*)(sp + j * 384 + 256 + h * 16 + 8);
        const __half2* pa = (const __half2*)&va;
        const __half2* pb = (const __half2*)&vb;
        #pragma unroll
        for (int u = 0; u < 4; u++) {
            float2 fa = __half22float2(pa[u]);
            float2 fb = __half22float2(pb[u]);
            o0[u * 2] += p0 * fa.x;     o0[u * 2 + 1] += p0 * fa.y;
            o0[8 + u * 2] += p0 * fb.x; o0[8 + u * 2 + 1] += p0 * fb.y;
            o1[u * 2] += p1 * fa.x;     o1[u * 2 + 1] += p1 * fa.y;
            o1[8 + u * 2] += p1 * fb.x; o1[8 + u * 2 + 1] += p1 * fb.y;
        }
    }

    const size_t rowbase = (size_t)(b * NNH + n) * LL + (size_t)w * WSZ;
    __align__(16) __half hv[16];
    #pragma unroll
    for (int d = 0; d < 8; d++)
        *(__half2*)(hv + d * 2) = __floats2half2_rn(o0[d * 2], o0[d * 2 + 1]);
    __half* d0 = g_attn + (rowbase + i0) * 128 + h * 16;
    *(uint4*)(d0)     = *(uint4*)(hv);
    *(uint4*)(d0 + 8) = *(uint4*)(hv + 8);
    #pragma unroll
    for (int d = 0; d < 8; d++)
        *(__half2*)(hv + d * 2) = __floats2half2_rn(o1[d * 2], o1[d * 2 + 1]);
    __half* d1 = g_attn + (rowbase + i1) * 128 + h * 16;
    *(uint4*)(d1)     = *(uint4*)(hv);
    *(uint4*)(d1 + 8) = *(uint4*)(hv + 8);
}

// ---------------------------------------------------------------------------
extern "C" void kernel_launch(void* const* d_in, const int* in_sizes, int n_in,
                              void* d_out, int out_size)
{
    const float* x      = (const float*)d_in[0];
    const float* qkv_w  = (const float*)d_in[1];
    const float* qkv_b  = (const float*)d_in[2];
    const float* proj_w = (const float*)d_in[3];
    const float* proj_b = (const float*)d_in[4];
    const float* fc1_w  = (const float*)d_in[5];
    const float* fc1_b  = (const float*)d_in[6];
    const float* fc2_w  = (const float*)d_in[7];
    const float* fc2_b  = (const float*)d_in[8];
    const float* g1     = (const float*)d_in[9];
    const float* b1     = (const float*)d_in[10];
    const float* g2     = (const float*)d_in[11];
    const float* b2     = (const float*)d_in[12];
    float* out = (float*)d_out;

    static bool attr_done = false;
    if (!attr_done) {
        cudaFuncSetAttribute(tc_gemm<0, 128>, cudaFuncAttributeMaxDynamicSharedMemorySize, SM128);
        cudaFuncSetAttribute(tc_gemm<1, 128>, cudaFuncAttributeMaxDynamicSharedMemorySize, SM128);
        cudaFuncSetAttribute(tc_gemm<2, 128>, cudaFuncAttributeMaxDynamicSharedMemorySize, SM128);
        cudaFuncSetAttribute(tc_gemm<3, 512>, cudaFuncAttributeMaxDynamicSharedMemorySize, SM512);
        attr_done = true;
    }

    const int MB = MTOK / 64; // 3060

    // 0) weight transpose to fp16 [N][K]; x gather/shift to fp16
    prep_w<<<(W_TOTAL + 255) / 256, 256>>>(qkv_w, proj_w, fc1_w, fc2_w);
    prep_x<<<MTOK / 8, 256>>>(x);
    // 1) QKV projection (streaming, 3 column blocks)
    tc_gemm<0, 128><<<dim3(MB, 3), 256, SM128>>>(OFF_QKV, qkv_b, nullptr, nullptr, nullptr);
    // 2) windowed attention (4 windows per block, fp16 smem, row-pair reuse)
    attn_kernel<<<BB * NNH * (NWIN / 4), 192>>>();
    // 3) proj + unshift + LN1 + residual(g_xh) -> x1h
    tc_gemm<1, 128><<<dim3(MB, 1), 256, SM128>>>(OFF_PROJ, proj_b, nullptr, g1, b1);
    // 4) fc1 + GELU
    tc_gemm<2, 128><<<dim3(MB, 4), 256, SM128>>>(OFF_FC1, fc1_b, nullptr, nullptr, nullptr);
    // 5) fc2 + LN2 + residual(x1h) + scatter to (B,L,N,D)
    tc_gemm<3, 512><<<dim3(MB, 1), 256, SM512>>>(OFF_FC2, fc2_b, out, g2, b2);
}